// round 4
// baseline (speedup 1.0000x reference)
#include <cuda_runtime.h>
#include <cstdint>

#define B_  8192
#define T_  16
#define K_  512
#define D_  128
#define BM  64          // rows (b) per CTA
#define KC  64          // codes per k-chunk
#define LDT 68          // padded smem row length (floats)
#define NCHUNK (K_/KC)  // 8
#define NCTA1 ((B_/BM)*T_)  // 2048
#define SMEM_BYTES (2*D_*LDT*4)  // zT + cT = 69632 B

#define NZQ  (B_*T_*D_)     // 16777216
#define NTOK (B_*T_)        // 131072

__device__ int            g_tokens[NTOK];
__device__ float          g_cnorm[T_*K_];
__device__ unsigned char  g_used[T_*K_];
__device__ float          g_partial[NCTA1];

// ---------------- f32x2 packed helpers (Blackwell dual-fp32 pipe) ----------------
__device__ __forceinline__ unsigned long long fma2(unsigned long long a,
                                                   unsigned long long b,
                                                   unsigned long long c) {
    unsigned long long d;
    asm("fma.rn.f32x2 %0, %1, %2, %3;" : "=l"(d) : "l"(a), "l"(b), "l"(c));
    return d;
}
__device__ __forceinline__ unsigned long long bcast2(float x) {
    unsigned long long d; unsigned u = __float_as_uint(x);
    asm("mov.b64 %0, {%1, %1};" : "=l"(d) : "r"(u));
    return d;
}
__device__ __forceinline__ unsigned long long packf2(float lo, float hi) {
    unsigned long long d; unsigned a = __float_as_uint(lo), b = __float_as_uint(hi);
    asm("mov.b64 %0, {%1, %2};" : "=l"(d) : "r"(a), "r"(b));
    return d;
}
__device__ __forceinline__ float2 unpk2(unsigned long long v) {
    unsigned lo, hi;
    asm("mov.b64 {%0, %1}, %2;" : "=r"(lo), "=r"(hi) : "l"(v));
    float2 r; r.x = __uint_as_float(lo); r.y = __uint_as_float(hi); return r;
}

// ---------------- prep: codebook norms + clear used bitmap ----------------
__global__ void k_prep(const float* __restrict__ cb) {
    int gt = blockIdx.x * blockDim.x + threadIdx.x;
    int w = gt >> 5, lane = gt & 31;                  // one warp per (t,k) row
    const float4* row = (const float4*)(cb + (size_t)w * D_);
    float4 v = row[lane];
    float s = v.x*v.x + v.y*v.y + v.z*v.z + v.w*v.w;
    #pragma unroll
    for (int o = 16; o; o >>= 1) s += __shfl_xor_sync(0xffffffffu, s, o);
    if (lane == 0) { g_cnorm[w] = s; g_used[w] = 0; }
}

// ---------------- transposed tile loader: dst[d*LDT + r] = src[r*stride + d] ----------------
__device__ __forceinline__ void load_tile_T(float* dst, const float* __restrict__ src,
                                            int src_stride /*floats*/) {
    int tid = threadIdx.x;
    int w = tid >> 5, l = tid & 31;
    int d4 = 4 * w + (l >> 3);   // 0..31 -> d = 4*d4
    int r0 = l & 7;
    #pragma unroll
    for (int r = r0; r < BM; r += 8) {
        float4 v = *(const float4*)(src + (size_t)r * src_stride + 4 * d4);
        dst[(4*d4 + 0) * LDT + r] = v.x;
        dst[(4*d4 + 1) * LDT + r] = v.y;
        dst[(4*d4 + 2) * LDT + r] = v.z;
        dst[(4*d4 + 3) * LDT + r] = v.w;
    }
}

// ---------------- main: fused GEMM + argmin (reference-exact distance) ----------------
__global__ void __launch_bounds__(256, 3) k_main(const float* __restrict__ ze,
                                                 const float* __restrict__ cb) {
    extern __shared__ float sm[];
    float* zT = sm;                 // [128][LDT] : zT[d][r]
    float* cT = sm + D_ * LDT;      // [128][LDT] : cT[d][k]
    __shared__ float red[BM];
    __shared__ float znrow[BM];     // ||z||^2 per local row

    const int tid = threadIdx.x;
    const int bx = blockIdx.x;      // b tile
    const int t  = blockIdx.y;      // 0..15
    const int ty = tid >> 4;        // rows 4*ty..4*ty+3
    const int tx = tid & 15;        // codes 4*tx..4*tx+3 within chunk

    load_tile_T(zT, ze + ((size_t)(bx * BM) * T_ + t) * D_, T_ * D_);
    __syncthreads();

    // per-row ||z||^2 BEFORE the argmin loop (enters the distance formula)
    #pragma unroll
    for (int r = 0; r < 4; r++) {
        int row = 4 * ty + r;
        float zn = 0.f;
        for (int d = tx; d < D_; d += 16) {
            float z = zT[d * LDT + row];
            zn = fmaf(z, z, zn);
        }
        #pragma unroll
        for (int off = 8; off >= 1; off >>= 1)
            zn += __shfl_xor_sync(0xffffffffu, zn, off);
        if (tx == 0) znrow[row] = zn;
    }

    float bestv[4] = {3.4e38f, 3.4e38f, 3.4e38f, 3.4e38f};
    int   bidx[4]  = {0, 0, 0, 0};

    for (int kc = 0; kc < NCHUNK; kc++) {
        __syncthreads();   // protect cT reuse; first iter: covers znrow publish
        load_tile_T(cT, cb + ((size_t)(t * K_ + kc * KC)) * D_, D_);
        __syncthreads();

        unsigned long long acc[4][2];
        #pragma unroll
        for (int r = 0; r < 4; r++) { acc[r][0] = 0ull; acc[r][1] = 0ull; }

        const float* zp = zT + 4 * ty;
        const float* cp = cT + 4 * tx;
        #pragma unroll 4
        for (int d = 0; d < D_; d++) {   // strict in-order fp32 FMA chain per (r,k)
            float4 zv = *(const float4*)(zp + d * LDT);
            float4 cv = *(const float4*)(cp + d * LDT);
            unsigned long long c01 = packf2(cv.x, cv.y);
            unsigned long long c23 = packf2(cv.z, cv.w);
            unsigned long long z0 = bcast2(zv.x), z1 = bcast2(zv.y);
            unsigned long long z2 = bcast2(zv.z), z3 = bcast2(zv.w);
            acc[0][0] = fma2(z0, c01, acc[0][0]);  acc[0][1] = fma2(z0, c23, acc[0][1]);
            acc[1][0] = fma2(z1, c01, acc[1][0]);  acc[1][1] = fma2(z1, c23, acc[1][1]);
            acc[2][0] = fma2(z2, c01, acc[2][0]);  acc[2][1] = fma2(z2, c23, acc[2][1]);
            acc[3][0] = fma2(z3, c01, acc[3][0]);  acc[3][1] = fma2(z3, c23, acc[3][1]);
        }

        const int kb = kc * KC + 4 * tx;
        const float cn0 = g_cnorm[t * K_ + kb + 0];
        const float cn1 = g_cnorm[t * K_ + kb + 1];
        const float cn2 = g_cnorm[t * K_ + kb + 2];
        const float cn3 = g_cnorm[t * K_ + kb + 3];
        #pragma unroll
        for (int r = 0; r < 4; r++) {
            float zn = znrow[4 * ty + r];
            float2 s01 = unpk2(acc[r][0]);
            float2 s23 = unpk2(acc[r][1]);
            // reference formula order: (||z||^2 - 2*s) + ||c||^2, fp32 each step
            float v0 = (zn - 2.f * s01.x) + cn0;
            float v1 = (zn - 2.f * s01.y) + cn1;
            float v2 = (zn - 2.f * s23.x) + cn2;
            float v3 = (zn - 2.f * s23.y) + cn3;
            float bv = v0; int bi = kb;
            if (v1 < bv) { bv = v1; bi = kb + 1; }
            if (v2 < bv) { bv = v2; bi = kb + 2; }
            if (v3 < bv) { bv = v3; bi = kb + 3; }
            #pragma unroll
            for (int off = 8; off >= 1; off >>= 1) {   // lowest-index tie-break
                float ov = __shfl_xor_sync(0xffffffffu, bv, off);
                int   oi = __shfl_xor_sync(0xffffffffu, bi, off);
                if (ov < bv || (ov == bv && oi < bi)) { bv = ov; bi = oi; }
            }
            if (bv < bestv[r] || (bv == bestv[r] && bi < bidx[r])) { bestv[r] = bv; bidx[r] = bi; }
        }
    }

    #pragma unroll
    for (int r = 0; r < 4; r++) {
        if (tx == 0) {
            int row = 4 * ty + r;
            int b = bx * BM + row;
            g_tokens[b * T_ + t] = bidx[r];
            g_used[t * K_ + bidx[r]] = 1;
            red[row] = bestv[r];          // d_best = ||z - c*||^2 (+ tiny fp noise)
        }
    }
    __syncthreads();
    if (tid == 0) {
        float s = 0.f;
        #pragma unroll 8
        for (int i = 0; i < BM; i++) s += red[i];
        g_partial[blockIdx.y * (B_ / BM) + bx] = s;
    }
}

// ---------------- z_q_st = z_e + (z_q - z_e), elementwise fp32 (reference-exact) ----------------
__global__ void k_copy(const float* __restrict__ ze, const float* __restrict__ cb,
                       float* __restrict__ out) {
    int row  = blockIdx.x * 8 + (threadIdx.x >> 5);   // row = b*T_ + t
    int lane = threadIdx.x & 31;
    int t = row & (T_ - 1);
    int tok = g_tokens[row];
    const float4* csrc = (const float4*)(cb + ((size_t)(t * K_ + tok)) * D_);
    const float4* zsrc = (const float4*)(ze + (size_t)row * D_);
    float4* dst = (float4*)(out + (size_t)row * D_);
    float4 c = csrc[lane];
    float4 z = zsrc[lane];
    float4 o;
    o.x = z.x + (c.x - z.x);
    o.y = z.y + (c.y - z.y);
    o.z = z.z + (c.z - z.z);
    o.w = z.w + (c.w - z.w);
    dst[lane] = o;
    if (lane == 0) out[NZQ + row] = (float)tok;
}

// ---------------- scalars: loss + utilization ----------------
__global__ void k_final(float* __restrict__ out) {
    __shared__ double ds[256];
    __shared__ int    dc[256];
    int tid = threadIdx.x;
    double s = 0.0;
    for (int i = tid; i < NCTA1; i += 256) s += (double)g_partial[i];
    int c = 0;
    for (int i = tid; i < T_ * K_; i += 256) c += g_used[i];
    ds[tid] = s; dc[tid] = c;
    __syncthreads();
    if (tid == 0) {
        double ts = 0.0; int tc = 0;
        for (int i = 0; i < 256; i++) { ts += ds[i]; tc += dc[i]; }
        out[NZQ + NTOK + 0] = (float)(0.25 * ts / (double)NZQ);
        out[NZQ + NTOK + 1] = (float)tc / (float)(T_ * K_);
    }
}

extern "C" void kernel_launch(void* const* d_in, const int* in_sizes, int n_in,
                              void* d_out, int out_size) {
    const float* ze = (const float*)d_in[0];
    const float* cb = (const float*)d_in[1];
    float* out = (float*)d_out;

    cudaFuncSetAttribute(k_main, cudaFuncAttributeMaxDynamicSharedMemorySize, SMEM_BYTES);

    k_prep<<<1024, 256>>>(cb);
    dim3 g1(B_ / BM, T_);
    k_main<<<g1, 256, SMEM_BYTES>>>(ze, cb);
    k_copy<<<NTOK / 8, 256>>>(ze, cb, out);
    k_final<<<1, 256>>>(out);
}